// round 1
// baseline (speedup 1.0000x reference)
#include <cuda_runtime.h>
#include <cuda_bf16.h>
#include <cstdint>

// Problem constants
#define Bsz 8
#define Dm  4096
#define D3  12288     // 3*D
#define Ssz 16
#define FFm 16384

// ---------------- scratch (allocation-free: __device__ globals) ----------------
__device__ float g_xn  [Bsz * Dm];   // rmsnorm(x)
__device__ float g_z   [Bsz * D3];   // xn @ proj_w   (atomic accum)
__device__ float g_y   [Bsz * Dm];   // gated output
__device__ float g_xout[Bsz * Dm];   // y@out_w + out_b + x (atomic accum)
__device__ float g_xn2 [Bsz * Dm];   // rmsnorm(xout)
__device__ float g_g1  [Bsz * FFm];  // xn2 @ mlp_w1  (atomic accum)
__device__ float g_g3  [Bsz * FFm];  // xn2 @ mlp_w3  (atomic accum)
__device__ float g_h   [Bsz * FFm];  // silu(g1)*g3

// ---------------- packed f32x2 helpers ----------------
__device__ __forceinline__ unsigned long long pack2(float lo, float hi) {
    unsigned long long r;
    asm("mov.b64 %0, {%1, %2};" : "=l"(r) : "r"(__float_as_uint(lo)), "r"(__float_as_uint(hi)));
    return r;
}
__device__ __forceinline__ void unpack2(unsigned long long v, float& lo, float& hi) {
    unsigned ulo, uhi;
    asm("mov.b64 {%0, %1}, %2;" : "=r"(ulo), "=r"(uhi) : "l"(v));
    lo = __uint_as_float(ulo); hi = __uint_as_float(uhi);
}

// ---------------- generic batched (B=8) split-K GEMV ----------------
// W: [K, N] row-major (N contiguous). out[b,n] += sum_k xin[b,k]*W[k,n]
// 256 threads per block: thread <-> output column. grid = (N/256, K/KCHUNK).
template<int KCHUNK>
__device__ __forceinline__ void gemv_body(const float* __restrict__ W,
                                          const float* __restrict__ xin,
                                          float* __restrict__ out,
                                          int K, int N) {
    __shared__ __align__(16) float xs[KCHUNK * 8];   // xs[k*8 + b]
    const int n  = blockIdx.x * 256 + threadIdx.x;
    const int k0 = blockIdx.y * KCHUNK;

    for (int t = threadIdx.x; t < KCHUNK * 8; t += 256) {
        int k = t >> 3, b = t & 7;
        xs[t] = xin[b * K + k0 + k];
    }
    __syncthreads();

    unsigned long long acc[4];
#pragma unroll
    for (int j = 0; j < 4; j++) acc[j] = pack2(0.f, 0.f);

    const float* Wp = W + (size_t)k0 * N + n;
#pragma unroll 4
    for (int k = 0; k < KCHUNK; k++) {
        float w = Wp[(size_t)k * N];
        unsigned long long w2;
        asm("mov.b64 %0, {%1, %1};" : "=l"(w2) : "r"(__float_as_uint(w)));
        const unsigned long long* xp = reinterpret_cast<const unsigned long long*>(xs + k * 8);
#pragma unroll
        for (int j = 0; j < 4; j++)
            asm("fma.rn.f32x2 %0, %1, %2, %0;" : "+l"(acc[j]) : "l"(w2), "l"(xp[j]));
    }

#pragma unroll
    for (int j = 0; j < 4; j++) {
        float lo, hi;
        unpack2(acc[j], lo, hi);
        atomicAdd(&out[(2 * j)     * N + n], lo);
        atomicAdd(&out[(2 * j + 1) * N + n], hi);
    }
}

__global__ void k_gemv_proj(const float* __restrict__ W) { gemv_body<512>(W, g_xn,  g_z,    Dm,  D3);  }
__global__ void k_gemv_out (const float* __restrict__ W) { gemv_body<256>(W, g_y,   g_xout, Dm,  Dm);  }
__global__ void k_gemv_w1  (const float* __restrict__ W) { gemv_body<512>(W, g_xn2, g_g1,   Dm,  FFm); }
__global__ void k_gemv_w3  (const float* __restrict__ W) { gemv_body<512>(W, g_xn2, g_g3,   Dm,  FFm); }
__global__ void k_gemv_w2  (const float* __restrict__ W, float* __restrict__ out_x) {
    gemv_body<512>(W, g_h, out_x, FFm, Dm);
}

// ---------------- rmsnorm ----------------
__device__ __forceinline__ void rmsnorm_body(const float* __restrict__ xr,
                                             const float* __restrict__ w,
                                             float* __restrict__ xo) {
    float ss = 0.f;
    for (int i = threadIdx.x; i < Dm; i += blockDim.x) { float v = xr[i]; ss += v * v; }
#pragma unroll
    for (int o = 16; o; o >>= 1) ss += __shfl_xor_sync(0xffffffffu, ss, o);
    __shared__ float red[32];
    int wid = threadIdx.x >> 5, lane = threadIdx.x & 31;
    if (lane == 0) red[wid] = ss;
    __syncthreads();
    int nw = blockDim.x >> 5;
    if (wid == 0) {
        float t = (lane < nw) ? red[lane] : 0.f;
#pragma unroll
        for (int o = 16; o; o >>= 1) t += __shfl_xor_sync(0xffffffffu, t, o);
        if (lane == 0) red[0] = t;
    }
    __syncthreads();
    float scale = rsqrtf(red[0] * (1.f / Dm) + 1e-6f);
    for (int i = threadIdx.x; i < Dm; i += blockDim.x) xo[i] = xr[i] * scale * w[i];
}

__global__ void k_rmsnorm_pre(const float* __restrict__ x, const float* __restrict__ w) {
    int b = blockIdx.x;
    rmsnorm_body(x + b * Dm, w, g_xn + b * Dm);
}
__global__ void k_rmsnorm_post(const float* __restrict__ w) {
    int b = blockIdx.x;
    rmsnorm_body(g_xout + b * Dm, w, g_xn2 + b * Dm);
}

// ---------------- init: zero atomic accumulators, seed xout = x + out_b ----------------
__global__ void k_init(const float* __restrict__ x, const float* __restrict__ out_b) {
    int i = blockIdx.x * blockDim.x + threadIdx.x;      // 131072 threads
    if (i < Bsz * D3)  g_z[i] = 0.f;
    if (i < Bsz * FFm) { g_g1[i] = 0.f; g_g3[i] = 0.f; }
    if (i < Bsz * Dm)  g_xout[i] = x[i] + out_b[i & (Dm - 1)];
}

// ---------------- FIR taps + gating + IIR update ----------------
// one thread per (b, d); each covers 3 projection channels (x2, x1, v)
__global__ void k_fir_iir(const float* __restrict__ fir_state,
                          const float* __restrict__ iir_state,
                          const float* __restrict__ sf_weight,
                          const float* __restrict__ sf_bias,
                          const float* __restrict__ D_res,
                          const float* __restrict__ residues,
                          const float* __restrict__ log_poles,
                          float* __restrict__ out_fir,
                          float* __restrict__ out_iir) {
    int idx = blockIdx.x * blockDim.x + threadIdx.x;   // [0, 32768)
    int b = idx >> 12;
    int d = idx & (Dm - 1);
    int head = d >> 7;
    int i    = d & 127;
    int base = head * 384 + i;

    float zp[3];
#pragma unroll
    for (int j = 0; j < 3; j++) {
        int n3 = base + j * 128;
        float u  = g_z[b * D3 + n3];
        float f0 = fir_state[(b * D3 + n3) * 2 + 0];
        float f1 = fir_state[(b * D3 + n3) * 2 + 1];
        const float* wr = sf_weight + n3 * 3;
        zp[j] = wr[2] * u + f0 * wr[0] + f1 * wr[1] + sf_bias[n3];
        out_fir[(b * D3 + n3) * 2 + 0] = f1;
        out_fir[(b * D3 + n3) * 2 + 1] = u;
    }
    float x2 = zp[0], x1 = zp[1], v = zp[2];
    float x1v = x1 * v;
    float res = 0.f;
#pragma unroll
    for (int s = 0; s < Ssz; s++) {
        float pole = expf(log_poles[d * Ssz + s]);
        float ni   = pole * iir_state[(b * Dm + d) * Ssz + s] + x1v;
        out_iir[(b * Dm + d) * Ssz + s] = ni;
        res += residues[d * Ssz + s] * ni;
    }
    g_y[b * Dm + d] = x2 * (res + D_res[d] * x1v);
}

// ---------------- silu gate + seed final output with xout ----------------
__global__ void k_silu(float* __restrict__ out_x) {
    int i = blockIdx.x * blockDim.x + threadIdx.x;     // 131072 threads
    if (i < Bsz * FFm) {
        float a = g_g1[i];
        g_h[i] = (a / (1.f + expf(-a))) * g_g3[i];
    }
    if (i < Bsz * Dm) out_x[i] = g_xout[i];
}

// ---------------- launcher ----------------
extern "C" void kernel_launch(void* const* d_in, const int* in_sizes, int n_in,
                              void* d_out, int out_size) {
    const float* x           = (const float*)d_in[0];
    const float* fir_state   = (const float*)d_in[1];
    const float* iir_state   = (const float*)d_in[2];
    const float* pre_norm_w  = (const float*)d_in[3];
    const float* proj_w      = (const float*)d_in[4];
    const float* sf_weight   = (const float*)d_in[5];
    const float* sf_bias     = (const float*)d_in[6];
    const float* D_res       = (const float*)d_in[7];
    const float* residues    = (const float*)d_in[8];
    const float* log_poles   = (const float*)d_in[9];
    const float* out_w       = (const float*)d_in[10];
    const float* out_b       = (const float*)d_in[11];
    const float* post_norm_w = (const float*)d_in[12];
    const float* mlp_w1      = (const float*)d_in[13];
    const float* mlp_w3      = (const float*)d_in[14];
    const float* mlp_w2      = (const float*)d_in[15];

    float* out_x   = (float*)d_out;                    // [8, 1, 4096]
    float* out_fir = out_x + Bsz * Dm;                 // [8, 12288, 2]
    float* out_iir = out_fir + Bsz * D3 * 2;           // [8, 4096, 16]

    k_init        <<<512, 256>>>(x, out_b);
    k_rmsnorm_pre <<<Bsz, 1024>>>(x, pre_norm_w);
    k_gemv_proj   <<<dim3(D3 / 256, Dm / 512), 256>>>(proj_w);
    k_fir_iir     <<<(Bsz * Dm) / 256, 256>>>(fir_state, iir_state, sf_weight, sf_bias,
                                              D_res, residues, log_poles, out_fir, out_iir);
    k_gemv_out    <<<dim3(Dm / 256, Dm / 256), 256>>>(out_w);
    k_rmsnorm_post<<<Bsz, 1024>>>(post_norm_w);
    k_gemv_w1     <<<dim3(FFm / 256, Dm / 512), 256>>>(mlp_w1);
    k_gemv_w3     <<<dim3(FFm / 256, Dm / 512), 256>>>(mlp_w3);
    k_silu        <<<512, 256>>>(out_x);
    k_gemv_w2     <<<dim3(Dm / 256, FFm / 512), 256>>>(mlp_w2, out_x);
}